// round 17
// baseline (speedup 1.0000x reference)
#include <cuda_runtime.h>
#include <cuda_fp16.h>
#include <cstdint>

#define B_    1024
#define T_    256
#define D_    64
#define H_    128
#define GC    384

__device__ __half g_xproj[(size_t)B_ * T_ * GC];   // fp16 x-projections (~201MB)
__device__ int    g_order[B_];
__device__ uint2  g_bfx[6144];    // Phase-A W fragments (fp16), [48nt][4ks][32ln]

__device__ __forceinline__ float sigmoidf_(float x) {
    return __fdividef(1.0f, 1.0f + __expf(-x));
}
__device__ __forceinline__ float tanhf_(float x) {
    return 1.0f - __fdividef(2.0f, __expf(2.0f * x) + 1.0f);
}

// ---------------- warp-level fp16 MMA (f32 accum) ----------------
__device__ __forceinline__ void mma16816(float* d, const uint32_t* a, uint32_t b0, uint32_t b1) {
    asm volatile(
        "mma.sync.aligned.m16n8k16.row.col.f32.f16.f16.f32 "
        "{%0,%1,%2,%3}, {%4,%5,%6,%7}, {%8,%9}, {%0,%1,%2,%3};"
        : "+f"(d[0]), "+f"(d[1]), "+f"(d[2]), "+f"(d[3])
        : "r"(a[0]), "r"(a[1]), "r"(a[2]), "r"(a[3]), "r"(b0), "r"(b1));
}

__device__ __forceinline__ uint32_t pack_h2(float x, float y) {
    __half2 h = __floats2half2_rn(x, y);
    return *reinterpret_cast<uint32_t*>(&h);
}
__device__ __forceinline__ uint32_t split_pack_h(float x, float y, uint32_t& lo) {
    __half hx = __float2half_rn(x), hy = __float2half_rn(y);
    float rx = x - __half2float(hx), ry = y - __half2float(hy);
    __half2 hp = __halves2half2(hx, hy);
    __half2 lp = __floats2half2_rn(rx, ry);
    lo = *reinterpret_cast<uint32_t*>(&lp);
    return *reinterpret_cast<uint32_t*>(&hp);
}

// B-fragment builder (fp16) for RECURRENT W rows (64+k)
__device__ __forceinline__ uint2 frag_make(const float* W, int ldn, int nt, int ks, int ln) {
    int g = ln >> 2, tg = ln & 3;
    int n = 8 * nt + g, k0 = 16 * ks + 2 * tg;
    uint32_t h0 = pack_h2(W[(64 + k0)     * ldn + n], W[(64 + k0 + 1) * ldn + n]);
    uint32_t h1 = pack_h2(W[(64 + k0 + 8) * ldn + n], W[(64 + k0 + 9) * ldn + n]);
    return make_uint2(h0, h1);
}

// B-fragment builder (fp16) for X-PART W rows (0..63)
__device__ __forceinline__ uint2 frag_make_x(const float* gkp, const float* ckp,
                                             int nt, int ks, int ln) {
    int g = ln >> 2, tg = ln & 3;
    int n = 8 * nt + g, k0 = 16 * ks + 2 * tg;
    float w00, w01, w10, w11;
    if (n < 256) {
        w00 = gkp[k0 * 256 + n];       w01 = gkp[(k0 + 1) * 256 + n];
        w10 = gkp[(k0 + 8) * 256 + n]; w11 = gkp[(k0 + 9) * 256 + n];
    } else {
        int m = n - 256;
        w00 = ckp[k0 * 128 + m];       w01 = ckp[(k0 + 1) * 128 + m];
        w10 = ckp[(k0 + 8) * 128 + m]; w11 = ckp[(k0 + 9) * 128 + m];
    }
    return make_uint2(pack_h2(w00, w01), pack_h2(w10, w11));
}

// ---------------- setup: sort (block 0) + Phase-A weight frag build (block 1) ----------
__global__ void setup_kernel(const int* __restrict__ seq_lens,
                             const float* __restrict__ gk, const float* __restrict__ ck) {
    int tid = threadIdx.x;
    if (blockIdx.x == 0) {
        __shared__ int hist[T_];
        __shared__ int offs[T_];
        for (int i = tid; i < T_; i += 256) hist[i] = 0;
        __syncthreads();
        for (int i = tid; i < B_; i += 256) atomicAdd(&hist[T_ - 1 - seq_lens[i]], 1);
        __syncthreads();
        if (tid == 0) { int s = 0; for (int k = 0; k < T_; k++) { offs[k] = s; s += hist[k]; } }
        __syncthreads();
        for (int i = tid; i < T_; i += 256) hist[i] = 0;
        __syncthreads();
        for (int i = tid; i < B_; i += 256) {
            int key = T_ - 1 - seq_lens[i];
            g_order[offs[key] + atomicAdd(&hist[key], 1)] = i;
        }
    } else {
        for (int idx = tid; idx < 6144; idx += 256) {
            int nt = idx >> 7, ks = (idx >> 5) & 3, ln = idx & 31;
            g_bfx[idx] = frag_make_x(gk, ck, nt, ks, ln);
        }
    }
}

// ---------------- Phase A v4: fp16 single pass, per-warp len skip ----------------
static constexpr int BIAS_OFF = 0;        // 384 f32
static constexpr int AH_OFF   = 1536;     // [128][72] fp16
static constexpr int PA_SMEM  = 20096;
#define SA 72

__global__ void __launch_bounds__(256, 4) xproj_mma_kernel(
    const int* __restrict__ item_his, const int* __restrict__ seq_lens,
    const float* __restrict__ emb,
    const float* __restrict__ gb, const float* __restrict__ cb)
{
    extern __shared__ char dynsmem[];
    float*  sBias = (float*)(dynsmem + BIAS_OFF);
    __half* sAh   = (__half*)(dynsmem + AH_OFF);

    int b  = blockIdx.x >> 1;
    int t0 = (blockIdx.x & 1) << 7;
    int len = seq_lens[b];
    if (t0 >= len) return;
    int mrows = len - t0;

    int tid = threadIdx.x;

    for (int i = tid; i < GC; i += 256) sBias[i] = (i < 256) ? gb[i] : cb[i - 256];

    {
        int r = tid >> 1, half = tid & 1;
        int item = item_his[b * T_ + t0 + r];
        const float4* e4 = reinterpret_cast<const float4*>(emb + (size_t)item * D_ + half * 32);
        #pragma unroll
        for (int q = 0; q < 8; q += 2) {
            float4 v0 = e4[q], v1 = e4[q + 1];
            uint32_t p[4];
            p[0] = pack_h2(v0.x, v0.y);
            p[1] = pack_h2(v0.z, v0.w);
            p[2] = pack_h2(v1.x, v1.y);
            p[3] = pack_h2(v1.z, v1.w);
            int c0 = half * 32 + q * 4;
            *reinterpret_cast<uint4*>(&sAh[r * SA + c0]) = *reinterpret_cast<uint4*>(p);
        }
    }
    __syncthreads();

    int wid = tid >> 5, lane = tid & 31;
    int gid = lane >> 2, tig = lane & 3;
    int m0 = wid * 16;

    if (m0 >= mrows) return;

    uint32_t ah[4][4];
    #pragma unroll
    for (int ks = 0; ks < 4; ks++) {
        int c = ks * 16 + 2 * tig;
        ah[ks][0] = *reinterpret_cast<const uint32_t*>(&sAh[(m0+gid)   * SA + c]);
        ah[ks][1] = *reinterpret_cast<const uint32_t*>(&sAh[(m0+gid+8) * SA + c]);
        ah[ks][2] = *reinterpret_cast<const uint32_t*>(&sAh[(m0+gid)   * SA + c + 8]);
        ah[ks][3] = *reinterpret_cast<const uint32_t*>(&sAh[(m0+gid+8) * SA + c + 8]);
    }

    __half* outbase = g_xproj + ((size_t)b * T_ + t0) * GC;
    const uint2* __restrict__ fH = g_bfx;

    for (int nt = 0; nt < 48; nt += 2) {
        float acc0[4] = {0.f, 0.f, 0.f, 0.f};
        float acc1[4] = {0.f, 0.f, 0.f, 0.f};
        #pragma unroll
        for (int ks = 0; ks < 4; ks++) {
            uint2 bh0 = __ldg(&fH[(nt       * 4 + ks) * 32 + lane]);
            uint2 bh1 = __ldg(&fH[((nt + 1) * 4 + ks) * 32 + lane]);
            mma16816(acc0, ah[ks], bh0.x, bh0.y);
            mma16816(acc1, ah[ks], bh1.x, bh1.y);
        }
        #pragma unroll
        for (int p = 0; p < 2; p++) {
            float* acc = p ? acc1 : acc0;
            int ncol = (nt + p) * 8 + 2 * tig;
            float2 bias = *reinterpret_cast<const float2*>(&sBias[ncol]);
            uint32_t o0 = pack_h2(acc[0] + bias.x, acc[1] + bias.y);
            uint32_t o1 = pack_h2(acc[2] + bias.x, acc[3] + bias.y);
            *reinterpret_cast<uint32_t*>(&outbase[(size_t)(m0 + gid)     * GC + ncol]) = o0;
            *reinterpret_cast<uint32_t*>(&outbase[(size_t)(m0 + gid + 8) * GC + ncol]) = o1;
        }
    }
}

// ---------------- Phase B: fp16 GRU, 256 threads (half the crossbar traffic) ----------
// 128 CTAs x 8 rows, 8 warps. Warp w: gate n-tiles 4w..4w+3, cand n-tiles 2w..2w+1.
// Every thread: 8 gate cols + 4 hidden units. A-frags loaded once/phase, reused.
static constexpr int OFF_A    = 0;        // u32[8ks][32ln][4]  4096 B
static constexpr int OFF_R    = 4096;
static constexpr int OFF_H    = 8192;     // f32[8][132]        4224 B
static constexpr int OFF_U    = 12416;
static constexpr int OFF_META = 16640;
static constexpr int G_SMEM   = 16768;
#define HS 132

__global__ void __launch_bounds__(256, 1) gru_mma_kernel(
    const int* __restrict__ seq_lens,
    const float* __restrict__ gk, const float* __restrict__ ck,
    float* __restrict__ out)
{
    extern __shared__ char dynsmem[];
    uint32_t* sA = (uint32_t*)(dynsmem + OFF_A);
    uint32_t* sR = (uint32_t*)(dynsmem + OFF_R);
    float* sH = (float*)(dynsmem + OFF_H);
    float* sU = (float*)(dynsmem + OFF_U);
    int* srow = (int*)(dynsmem + OFF_META);
    int* slen = srow + 8;

    int tid = threadIdx.x;
    int wid = tid >> 5, lane = tid & 31;
    int gid = lane >> 2, tig = lane & 3;

    // weight fragments (fp16) -> registers: gate 4 nt, cand 2 nt
    uint2 BgH[4][8], BcH[2][8];
    #pragma unroll
    for (int ks = 0; ks < 8; ks++) {
        #pragma unroll
        for (int q = 0; q < 4; q++) BgH[q][ks] = frag_make(gk, 256, 4 * wid + q, ks, lane);
        #pragma unroll
        for (int p = 0; p < 2; p++) BcH[p][ks] = frag_make(ck, 128, 2 * wid + p, ks, lane);
    }
    for (int i = tid; i < 1024; i += 256) { sA[i] = 0u; sR[i] = 0u; }
    for (int i = tid; i < 8 * HS; i += 256) { sH[i] = 0.0f; sU[i] = 0.0f; }
    if (tid < 8) {
        int row = g_order[blockIdx.x * 8 + tid];
        srow[tid] = row;
        slen[tid] = seq_lens[row];
    }
    __syncthreads();

    int maxlen = slen[0];
    int mylen  = slen[gid];
    size_t myxoff = (size_t)srow[gid] * (T_ * GC);
    bool isR = (wid < 4);
    int gcBase = 32 * wid + 2 * tig;           // gate col base (this thread: +8q)
    int j0 = 16 * wid + 2 * tig;               // hidden-unit col pairs: j0, j0+8
    int rOff0 = ((2 * wid)     * 32 + lane) * 4;   // rh frag store (q0,q1)
    int rOff1 = ((2 * wid + 1) * 32 + lane) * 4;   // (q2,q3)
    int aOff  = (wid * 32 + lane) * 4;             // h frag store

    // preload x-projections for t = 0
    float2 xg[4], xc0 = make_float2(0.f, 0.f), xc1 = make_float2(0.f, 0.f);
    #pragma unroll
    for (int q = 0; q < 4; q++) xg[q] = make_float2(0.f, 0.f);
    if (0 < mylen) {
        #pragma unroll
        for (int q = 0; q < 4; q++)
            xg[q] = __half22float2(*reinterpret_cast<const __half2*>(&g_xproj[myxoff + gcBase + 8 * q]));
        xc0 = __half22float2(*reinterpret_cast<const __half2*>(&g_xproj[myxoff + 256 + j0]));
        xc1 = __half22float2(*reinterpret_cast<const __half2*>(&g_xproj[myxoff + 256 + j0 + 8]));
    }

    for (int t = 0; t < maxlen; t++) {
        // prefetch t+1
        float2 xgn[4], xc0n = make_float2(0.f, 0.f), xc1n = make_float2(0.f, 0.f);
        #pragma unroll
        for (int q = 0; q < 4; q++) xgn[q] = make_float2(0.f, 0.f);
        if (t + 1 < mylen) {
            size_t bn = myxoff + (size_t)(t + 1) * GC;
            #pragma unroll
            for (int q = 0; q < 4; q++)
                xgn[q] = __half22float2(*reinterpret_cast<const __half2*>(&g_xproj[bn + gcBase + 8 * q]));
            xc0n = __half22float2(*reinterpret_cast<const __half2*>(&g_xproj[bn + 256 + j0]));
            xc1n = __half22float2(*reinterpret_cast<const __half2*>(&g_xproj[bn + 256 + j0 + 8]));
        }
        bool act = (t < mylen);

        // ---- gate MMA: 4 n-tiles, A-frags loaded once per ks ----
        float acc[4][4];
        #pragma unroll
        for (int q = 0; q < 4; q++)
            #pragma unroll
            for (int e = 0; e < 4; e++) acc[q][e] = 0.f;
        #pragma unroll
        for (int ks = 0; ks < 8; ks++) {
            uint4 a4 = *reinterpret_cast<const uint4*>(&sA[(ks * 32 + lane) * 4]);
            const uint32_t* a = reinterpret_cast<const uint32_t*>(&a4);
            #pragma unroll
            for (int q = 0; q < 4; q++)
                mma16816(acc[q], a, BgH[q][ks].x, BgH[q][ks].y);
        }
        // gate combine: 8 sigmoids
        float sE[4], sO[4];
        #pragma unroll
        for (int q = 0; q < 4; q++) {
            sE[q] = sigmoidf_(acc[q][0] + acc[q][2] + xg[q].x);
            sO[q] = sigmoidf_(acc[q][1] + acc[q][3] + xg[q].y);
        }
        if (isR) {
            uint32_t hiL[4], loL[4];
            #pragma unroll
            for (int q = 0; q < 4; q++) {
                float2 h01 = *reinterpret_cast<const float2*>(&sH[gid * HS + gcBase + 8 * q]);
                hiL[q] = split_pack_h(sE[q] * h01.x, sO[q] * h01.y, loL[q]);
            }
            uint4 w0 = make_uint4(hiL[0], loL[0], hiL[1], loL[1]);
            uint4 w1 = make_uint4(hiL[2], loL[2], hiL[3], loL[3]);
            *reinterpret_cast<uint4*>(&sR[rOff0]) = w0;
            *reinterpret_cast<uint4*>(&sR[rOff1]) = w1;
        } else {
            #pragma unroll
            for (int q = 0; q < 4; q++)
                *reinterpret_cast<float2*>(&sU[gid * HS + gcBase - 128 + 8 * q]) = make_float2(sE[q], sO[q]);
        }
        __syncthreads();

        float2 uu0   = *reinterpret_cast<const float2*>(&sU[gid * HS + j0]);
        float2 uu1   = *reinterpret_cast<const float2*>(&sU[gid * HS + j0 + 8]);
        float2 hold0 = *reinterpret_cast<const float2*>(&sH[gid * HS + j0]);
        float2 hold1 = *reinterpret_cast<const float2*>(&sH[gid * HS + j0 + 8]);

        // ---- cand MMA: 2 n-tiles ----
        float c[2][4];
        #pragma unroll
        for (int p = 0; p < 2; p++)
            #pragma unroll
            for (int e = 0; e < 4; e++) c[p][e] = 0.f;
        #pragma unroll
        for (int ks = 0; ks < 8; ks++) {
            uint4 r4 = *reinterpret_cast<const uint4*>(&sR[(ks * 32 + lane) * 4]);
            const uint32_t* a = reinterpret_cast<const uint32_t*>(&r4);
            mma16816(c[0], a, BcH[0][ks].x, BcH[0][ks].y);
            mma16816(c[1], a, BcH[1][ks].x, BcH[1][ks].y);
        }

        // ---- update: this thread owns h[gid][j0, j0+1, j0+8, j0+9] ----
        if (act) {
            float cc00 = tanhf_(c[0][0] + c[0][2] + xc0.x);
            float cc01 = tanhf_(c[0][1] + c[0][3] + xc0.y);
            float cc10 = tanhf_(c[1][0] + c[1][2] + xc1.x);
            float cc11 = tanhf_(c[1][1] + c[1][3] + xc1.y);
            float hn00 = uu0.x * hold0.x + (1.0f - uu0.x) * cc00;
            float hn01 = uu0.y * hold0.y + (1.0f - uu0.y) * cc01;
            float hn10 = uu1.x * hold1.x + (1.0f - uu1.x) * cc10;
            float hn11 = uu1.y * hold1.y + (1.0f - uu1.y) * cc11;
            *reinterpret_cast<float2*>(&sH[gid * HS + j0])     = make_float2(hn00, hn01);
            *reinterpret_cast<float2*>(&sH[gid * HS + j0 + 8]) = make_float2(hn10, hn11);
            uint32_t lo0, lo1;
            uint32_t hi0 = split_pack_h(hn00, hn01, lo0);
            uint32_t hi1 = split_pack_h(hn10, hn11, lo1);
            *reinterpret_cast<uint4*>(&sA[aOff]) = make_uint4(hi0, lo0, hi1, lo1);
        }
        __syncthreads();

        #pragma unroll
        for (int q = 0; q < 4; q++) xg[q] = xgn[q];
        xc0 = xc0n; xc1 = xc1n;
    }

    // output: thread owns h[gid][j0..j0+1] and [j0+8..j0+9]
    float* orow = out + (size_t)srow[gid] * H_;
    *reinterpret_cast<float2*>(&orow[j0])     = *reinterpret_cast<const float2*>(&sH[gid * HS + j0]);
    *reinterpret_cast<float2*>(&orow[j0 + 8]) = *reinterpret_cast<const float2*>(&sH[gid * HS + j0 + 8]);
}

// ---------------- launch ----------------
extern "C" void kernel_launch(void* const* d_in, const int* in_sizes, int n_in,
                              void* d_out, int out_size) {
    const int*   item_his = (const int*)  d_in[0];
    const int*   seq_lens = (const int*)  d_in[1];
    const float* emb      = (const float*)d_in[2];
    const float* gk       = (const float*)d_in[3];
    const float* gb       = (const float*)d_in[4];
    const float* ck       = (const float*)d_in[5];
    const float* cb       = (const float*)d_in[6];
    float*       out      = (float*)d_out;

    cudaFuncSetAttribute(xproj_mma_kernel, cudaFuncAttributeMaxDynamicSharedMemorySize, PA_SMEM);
    cudaFuncSetAttribute(gru_mma_kernel,   cudaFuncAttributeMaxDynamicSharedMemorySize, G_SMEM);

    setup_kernel<<<2, 256>>>(seq_lens, gk, ck);
    xproj_mma_kernel<<<B_ * 2, 256, PA_SMEM>>>(item_his, seq_lens, emb, gb, cb);
    gru_mma_kernel<<<B_ / 8, 256, G_SMEM>>>(seq_lens, gk, ck, out);
}